// round 6
// baseline (speedup 1.0000x reference)
#include <cuda_runtime.h>

#define NB        10000
#define VOCAB     10000
#define SEQ       80
#define EMB       100
#define UNITS     64
#define RPW       8           // rows per warp = rows per block
#define NV2       32          // UNITS/2 k-pairs

// precomputed ETable[v][u] = emb[v] @ Wx[:,u] + b[u]
__device__ float g_etable[VOCAB * UNITS];

typedef unsigned long long u64;

__device__ __forceinline__ void fma2(u64& d, u64 a, u64 b) {
    asm("fma.rn.f32x2 %0, %1, %2, %0;" : "+l"(d) : "l"(a), "l"(b));
}
__device__ __forceinline__ u64 packf2(float lo, float hi) {
    u64 r; asm("mov.b64 %0, {%1, %2};" : "=l"(r) : "f"(lo), "f"(hi)); return r;
}
__device__ __forceinline__ float fold_tanh(u64 v) {
    float lo, hi;
    asm("mov.b64 {%0, %1}, %2;" : "=f"(lo), "=f"(hi) : "l"(v));
    float s = lo + hi, r;
    asm("tanh.approx.f32 %0, %1;" : "=f"(r) : "f"(s));
    return r;
}

// ============ kernel 1: ETable = emb @ Wx + b (one-shot, 64M MACs) ============
__global__ __launch_bounds__(256)
void build_etable(const float* __restrict__ emb,
                  const float* __restrict__ Wx,
                  const float* __restrict__ bias)
{
    const int w   = threadIdx.x >> 5;
    const int l   = threadIdx.x & 31;
    const int row = blockIdx.x * 8 + w;     // 1250 blocks * 8 = 10000 exact
    const int u   = l * 2;
    float2 acc = make_float2(bias[u], bias[u + 1]);
    const float* er = emb + row * EMB;
    #pragma unroll 4
    for (int e = 0; e < EMB; ++e) {
        float xe = __ldg(er + e);
        float2 wv = *(const float2*)(Wx + e * UNITS + u);
        acc.x = fmaf(xe, wv.x, acc.x);
        acc.y = fmaf(xe, wv.y, acc.y);
    }
    *(float2*)(g_etable + row * UNITS + u) = acc;
}

// ============ kernel 2: 1-warp blocks, Wh in registers, all-SM spread ============
__global__ __launch_bounds__(32, 10)
void rnn_scan(const int* __restrict__ tokens,
              const float* __restrict__ Wh,
              const float* __restrict__ Wfc,
              const float* __restrict__ bfc,
              float* __restrict__ out)
{
    __shared__ int   tokoff_s[SEQ][RPW];    // token offsets premultiplied by UNITS
    __shared__ float h_s[RPW][UNITS];

    const int l    = threadIdx.x;           // lane 0..31
    const int row0 = blockIdx.x * RPW;

    // ---- stage tokens (transposed [t][r]), pre-scaled to element offsets ----
    for (int i = l; i < SEQ * RPW; i += 32) {
        int t = i >> 3, r = i & 7;
        tokoff_s[t][r] = tokens[(row0 + r) * SEQ + t] * UNITS;
    }
    // ---- zero h ----
    for (int i = l; i < RPW * UNITS; i += 32)
        ((float*)h_s)[i] = 0.0f;

    // ---- Wh columns for units (2l, 2l+1), k-paired, into registers ----
    u64 wu0[NV2], wu1[NV2];
    const int u0 = 2 * l;
    #pragma unroll
    for (int k2 = 0; k2 < NV2; ++k2) {
        float2 a = *(const float2*)(Wh + (2 * k2)     * UNITS + u0);
        float2 b = *(const float2*)(Wh + (2 * k2 + 1) * UNITS + u0);
        wu0[k2] = packf2(a.x, b.x);
        wu1[k2] = packf2(a.y, b.y);
    }
    __syncwarp();   // tokens + h staged before use

    // ---- prefetch xp for t=0: coalesced LDG.64 per row ----
    u64 xpre[RPW];
    #pragma unroll
    for (int r = 0; r < RPW; ++r)
        xpre[r] = *(const u64*)(g_etable + tokoff_s[0][r] + u0);

    for (int t = 0; t < SEQ; ++t) {
        // init accumulators from prefetched xp (bias folded into ETable)
        u64 acc[RPW][2];
        #pragma unroll
        for (int r = 0; r < RPW; ++r) {
            float f0, f1;
            asm("mov.b64 {%0, %1}, %2;" : "=f"(f0), "=f"(f1) : "l"(xpre[r]));
            acc[r][0] = packf2(f0, 0.0f);
            acc[r][1] = packf2(f1, 0.0f);
        }

        // prefetch next step's xp (clamped; duplicate final load discarded)
        const int tn = (t + 1 < SEQ) ? (t + 1) : (SEQ - 1);
        #pragma unroll
        for (int r = 0; r < RPW; ++r)
            xpre[r] = *(const u64*)(g_etable + tokoff_s[tn][r] + u0);

        // ---- h @ Wh: h pairs broadcast from SMEM, weights from registers ----
        #pragma unroll
        for (int j = 0; j < 16; ++j) {          // 4 h values = k-pairs 2j, 2j+1
            #pragma unroll
            for (int r = 0; r < RPW; ++r) {
                ulonglong2 hv = *(const ulonglong2*)(&h_s[r][4 * j]); // broadcast
                fma2(acc[r][0], hv.x, wu0[2 * j]);
                fma2(acc[r][1], hv.x, wu1[2 * j]);
                fma2(acc[r][0], hv.y, wu0[2 * j + 1]);
                fma2(acc[r][1], hv.y, wu1[2 * j + 1]);
            }
        }

        __syncwarp();   // all broadcast reads of h done before overwrite
        #pragma unroll
        for (int r = 0; r < RPW; ++r) {
            float f0 = fold_tanh(acc[r][0]);
            float f1 = fold_tanh(acc[r][1]);
            *(u64*)(&h_s[r][2 * l]) = packf2(f0, f1);   // STS.64, conflict-free
        }
        __syncwarp();   // new h visible to all lanes before next step's reads
    }

    // ---- final FC + sigmoid: lanes 0..7 each handle one row ----
    if (l < RPW) {
        const float* hf = h_s[l];
        float dot = 0.0f;
        #pragma unroll 8
        for (int v = 0; v < UNITS; ++v) dot += hf[v] * __ldg(Wfc + v);
        float logit = dot + __ldg(bfc);
        out[row0 + l] = 1.0f / (1.0f + __expf(-logit));
    }
}

extern "C" void kernel_launch(void* const* d_in, const int* in_sizes, int n_in,
                              void* d_out, int out_size) {
    const int*   tokens = (const int*)  d_in[0];
    const float* emb    = (const float*)d_in[1];
    const float* Wx     = (const float*)d_in[2];
    const float* Wh     = (const float*)d_in[3];
    const float* b      = (const float*)d_in[4];
    const float* Wfc    = (const float*)d_in[5];
    const float* bfc    = (const float*)d_in[6];
    float* out          = (float*)d_out;

    build_etable<<<VOCAB / 8, 256>>>(emb, Wx, b);
    rnn_scan<<<NB / RPW, 32>>>(tokens, Wh, Wfc, bfc, out);
}